// round 5
// baseline (speedup 1.0000x reference)
#include <cuda_runtime.h>
#include <cuda_bf16.h>
#include <cstdint>

// ============================ problem constants ============================
#define B_ROWS   2048
#define DIM      128
#define NE       100000
#define NE_PAD   100096            // 782 * 128
#define CHUNKS   782
#define SPLITS   9
#define CPS      87                // ceil(782/9)
#define ROWTILES 16
#define SPLITS2  (SPLITS * 2)
#define SHIFT_C  96.0f
#define L2E      1.44269504088896f

// ============================ device scratch ===============================
__device__ __align__(16) uint32_t g_Aq[B_ROWS * 32];          // int8 packed
__device__ __align__(16) uint32_t g_Eq[(size_t)NE_PAD * 32];  // int8 packed
__device__ float g_sa[B_ROWS];           // A row scale
__device__ float g_seL[NE_PAD];          // E row scale * log2(e); pad = 0
__device__ float g_badj[NE_PAD];         // (bias - 96) * log2(e); pad = -1e30
__device__ float g_s[B_ROWS * SPLITS2];
__device__ float g_t[B_ROWS];
__device__ float g_red[16];

// ============================ PTX helpers ==================================
__device__ __forceinline__ uint32_t smem_to_u32(const void* smem_ptr) {
    uint32_t addr;
    asm("{ .reg .u64 tmp; cvta.to.shared.u64 tmp, %1; cvt.u32.u64 %0, tmp; }"
        : "=r"(addr) : "l"(smem_ptr));
    return addr;
}

__device__ __forceinline__ float ex2(float x) {
    float y;
    asm("ex2.approx.f32 %0, %1;" : "=f"(y) : "f"(x));
    return y;
}

__device__ __forceinline__ void cp16(uint32_t saddr, const void* gaddr) {
    asm volatile("cp.async.cg.shared.global [%0], [%1], 16;"
                 :: "r"(saddr), "l"(gaddr) : "memory");
}
#define CP_COMMIT() asm volatile("cp.async.commit_group;" ::: "memory")
#define CP_WAIT0()  asm volatile("cp.async.wait_group 0;" ::: "memory")

__device__ __forceinline__ void ldsm4(uint32_t* r, uint32_t addr) {
    asm volatile("ldmatrix.sync.aligned.m8n8.x4.shared.b16 {%0,%1,%2,%3}, [%4];"
                 : "=r"(r[0]), "=r"(r[1]), "=r"(r[2]), "=r"(r[3]) : "r"(addr));
}

// int8 tensor op: m16n8k32, s32 accumulate
__device__ __forceinline__ void mma_s8(int& d0, int& d1, int& d2, int& d3,
                                       uint32_t a0, uint32_t a1, uint32_t a2, uint32_t a3,
                                       uint32_t b0, uint32_t b1) {
    asm volatile(
        "mma.sync.aligned.m16n8k32.row.col.s32.s8.s8.s32 "
        "{%0,%1,%2,%3}, {%4,%5,%6,%7}, {%8,%9}, {%0,%1,%2,%3};"
        : "+r"(d0), "+r"(d1), "+r"(d2), "+r"(d3)
        : "r"(a0), "r"(a1), "r"(a2), "r"(a3), "r"(b0), "r"(b1));
}

// ============================ SMEM layout ==================================
// int8 rows: 128B data + 16B pad = 144B stride (conflict-free ldmatrix)
#define STRIDE   144
#define SM_A     0                       // 128 * 144 = 18432
#define SM_B0    18432
#define SM_B1    36864
#define SM_BIAS0 55296
#define SM_SEL0  55808
#define SM_BIAS1 56320
#define SM_SEL1  56832
#define SM_TOTAL 57344

// ==================== kernel 1: per-row int8 quantization ==================
// one warp per row; rows [0,2048) = A, rows [2048, 2048+NE_PAD) = E
__global__ void quant_kernel(const float* __restrict__ A,
                             const float* __restrict__ E,
                             const float* __restrict__ bias) {
    const int w    = (blockIdx.x * blockDim.x + threadIdx.x) >> 5;
    const int lane = threadIdx.x & 31;
    const int totalW = B_ROWS + NE_PAD;
    if (w >= totalW) return;

    const bool isA = (w < B_ROWS);
    const int  r   = isA ? w : (w - B_ROWS);
    const bool pad = (!isA) && (r >= NE);

    float4 v = make_float4(0.f, 0.f, 0.f, 0.f);
    if (!pad) {
        const float* src = isA ? (A + (size_t)r * DIM) : (E + (size_t)r * DIM);
        v = *(const float4*)(src + lane * 4);
    }
    float m = fmaxf(fmaxf(fabsf(v.x), fabsf(v.y)), fmaxf(fabsf(v.z), fabsf(v.w)));
    #pragma unroll
    for (int off = 16; off > 0; off >>= 1)
        m = fmaxf(m, __shfl_xor_sync(0xFFFFFFFFu, m, off));

    const float inv = (m > 0.f) ? (127.0f / m) : 0.f;
    const float scale = m * (1.0f / 127.0f);

    int q0 = max(-127, min(127, __float2int_rn(v.x * inv)));
    int q1 = max(-127, min(127, __float2int_rn(v.y * inv)));
    int q2 = max(-127, min(127, __float2int_rn(v.z * inv)));
    int q3 = max(-127, min(127, __float2int_rn(v.w * inv)));
    uint32_t packed = (uint32_t)(q0 & 0xFF) | ((uint32_t)(q1 & 0xFF) << 8)
                    | ((uint32_t)(q2 & 0xFF) << 16) | ((uint32_t)(q3 & 0xFF) << 24);

    if (isA) {
        g_Aq[r * 32 + lane] = packed;
        if (lane == 0) g_sa[r] = scale;
    } else {
        g_Eq[(size_t)r * 32 + lane] = packed;
        if (lane == 0) {
            g_seL[r]  = pad ? 0.f : scale * L2E;
            g_badj[r] = pad ? -1e30f : (bias[r] - SHIFT_C) * L2E;
        }
    }
}

// ===================== kernel 2: target logits (fp32 exact) ================
__global__ void target_kernel(const float* __restrict__ A,
                              const float* __restrict__ E,
                              const float* __restrict__ bias,
                              const void* __restrict__ yraw) {
    int gwarp = (blockIdx.x * blockDim.x + threadIdx.x) >> 5;
    int lane  = threadIdx.x & 31;
    if (gwarp >= B_ROWS) return;

    const int* y32 = (const int*)yraw;
    bool is64 = (y32[1] == 0) && (y32[3] == 0) && (y32[5] == 0);
    long long idx;
    if (is64) idx = ((const long long*)yraw)[gwarp];
    else      idx = (long long)y32[gwarp];

    const float4* a = (const float4*)(A + (size_t)gwarp * DIM);
    const float4* e = (const float4*)(E + (size_t)idx * DIM);
    float4 av = a[lane];
    float4 ev = e[lane];
    float d = av.x * ev.x + av.y * ev.y + av.z * ev.z + av.w * ev.w;
    #pragma unroll
    for (int off = 16; off > 0; off >>= 1)
        d += __shfl_xor_sync(0xFFFFFFFFu, d, off);
    if (lane == 0)
        g_t[gwarp] = d + bias[idx];
}

// ================= kernel 3: fused INT8 GEMM + fixed-shift softmax =========
__device__ __forceinline__ void load_chunk(uint32_t sb, int buf, int eb, int tid) {
    uint32_t dstB = sb + (buf ? SM_B1 : SM_B0);
    const char* src = (const char*)g_Eq + (size_t)eb * DIM;   // int8 rows
    #pragma unroll
    for (int t = 0; t < 4; t++) {
        int idx = tid + t * 256;
        int r   = idx >> 3;          // entity row (128 rows x 8 segs)
        int seg = idx & 7;
        cp16(dstB + r * STRIDE + seg * 16, src + r * DIM + seg * 16);
    }
    if (tid < 32)
        cp16(sb + (buf ? SM_BIAS1 : SM_BIAS0) + tid * 16, g_badj + eb + tid * 4);
    else if (tid < 64)
        cp16(sb + (buf ? SM_SEL1 : SM_SEL0) + (tid - 32) * 16, g_seL + eb + (tid - 32) * 4);
}

__global__ void __launch_bounds__(256, 1) main_kernel() {
    extern __shared__ char smem[];
    const uint32_t sb = smem_to_u32(smem);
    const int tid  = threadIdx.x;
    const int lane = tid & 31;
    const int wid  = tid >> 5;
    const int wm   = wid & 3;        // warp row-tile (32 rows)
    const int wn   = wid >> 2;       // warp col-tile (64 cols)
    const int split   = blockIdx.x;
    const int rowtile = blockIdx.y;

    const int start = split * CPS;
    const int count = min(CPS, CHUNKS - start);

    // ---- async load A tile (128x128 int8) + chunk 0 ----
    {
        const char* Abase = (const char*)g_Aq + (size_t)rowtile * 128 * DIM;
        #pragma unroll
        for (int t = 0; t < 4; t++) {
            int idx = tid + t * 256;
            int r   = idx >> 3;
            int seg = idx & 7;
            cp16(sb + SM_A + r * STRIDE + seg * 16, Abase + r * DIM + seg * 16);
        }
    }
    load_chunk(sb, 0, start * 128, tid);
    CP_COMMIT();
    CP_WAIT0();
    __syncthreads();

    // ---- hoist A fragments: afr[ks][mi][4], ks = k32 step (4 steps) ----
    uint32_t afr[4][2][4];
    {
        int g = lane >> 3, i = lane & 7;
        int row_add = (g & 1) * 8 + i;
        int col_add = (g >> 1) * 16;       // byte offset within 32B k-group
        #pragma unroll
        for (int ks = 0; ks < 4; ks++)
            #pragma unroll
            for (int mi = 0; mi < 2; mi++) {
                int row = wm * 32 + mi * 16 + row_add;
                ldsm4(afr[ks][mi], sb + SM_A + row * STRIDE + ks * 32 + col_add);
            }
    }

    // per-slot A scales (slot = mi*2 + h)
    float sar[4];
    #pragma unroll
    for (int mi = 0; mi < 2; mi++)
        #pragma unroll
        for (int h = 0; h < 2; h++)
            sar[mi * 2 + h] = g_sa[rowtile * 128 + wm * 32 + mi * 16 + (lane >> 2) + h * 8];

    float s[4] = {0.f, 0.f, 0.f, 0.f};

    const int gB = lane >> 3, iB = lane & 7;
    const uint32_t bofs = (uint32_t)((wn * 64 + (gB >> 1) * 8 + iB) * STRIDE
                                     + (gB & 1) * 16);
    const int bcol = wn * 64 + (lane & 3) * 2;

    int acc0[2][4][4];                 // half 0: j 0..3
    int acc1[2][4][4];                 // half 1: j 4..7 (lives across chunks)
    float2 bzA[4], szA[4], bzB[4], szB[4];

    // EPI of one (mi-pair, j) slice: 8 values -> s[]
    auto epi = [&](int a0[4], int a1[4], float2 bz, float2 sz) {
        s[0] += ex2(fmaf(__int2float_rn(a0[0]) * sar[0], sz.x, bz.x));
        s[0] += ex2(fmaf(__int2float_rn(a0[1]) * sar[0], sz.y, bz.y));
        s[1] += ex2(fmaf(__int2float_rn(a0[2]) * sar[1], sz.x, bz.x));
        s[1] += ex2(fmaf(__int2float_rn(a0[3]) * sar[1], sz.y, bz.y));
        s[2] += ex2(fmaf(__int2float_rn(a1[0]) * sar[2], sz.x, bz.x));
        s[2] += ex2(fmaf(__int2float_rn(a1[1]) * sar[2], sz.y, bz.y));
        s[3] += ex2(fmaf(__int2float_rn(a1[2]) * sar[3], sz.x, bz.x));
        s[3] += ex2(fmaf(__int2float_rn(a1[3]) * sar[3], sz.y, bz.y));
    };

    for (int c = 0; c < count; ++c) {
        if (c + 1 < count)
            load_chunk(sb, (c + 1) & 1, (start + c + 1) * 128, tid);
        CP_COMMIT();

        const uint32_t sBcur = sb + ((c & 1) ? SM_B1 : SM_B0);
        const float* biasp = (const float*)(smem + ((c & 1) ? SM_BIAS1 : SM_BIAS0));
        const float* selp  = (const float*)(smem + ((c & 1) ? SM_SEL1 : SM_SEL0));

        // current-chunk bias/scale for j0..3 (consumed in half1 epi below)
        #pragma unroll
        for (int jj = 0; jj < 4; jj++) {
            bzA[jj] = *(const float2*)(biasp + bcol + jj * 8);
            szA[jj] = *(const float2*)(selp  + bcol + jj * 8);
        }

        // ---- half 0 MMA (j 0..3) interleaved with EPI(prev chunk half 1) ----
        #pragma unroll
        for (int mi = 0; mi < 2; mi++)
            #pragma unroll
            for (int jj = 0; jj < 4; jj++)
                #pragma unroll
                for (int e = 0; e < 4; e++)
                    acc0[mi][jj][e] = 0;

        #pragma unroll
        for (int ks = 0; ks < 4; ks++) {
            #pragma unroll
            for (int q = 0; q < 2; q++) {
                uint32_t r4[4];
                ldsm4(r4, sBcur + bofs + q * 16 * STRIDE + ks * 32);
                #pragma unroll
                for (int mi = 0; mi < 2; mi++) {
                    mma_s8(acc0[mi][2*q][0],   acc0[mi][2*q][1],
                           acc0[mi][2*q][2],   acc0[mi][2*q][3],
                           afr[ks][mi][0], afr[ks][mi][1], afr[ks][mi][2], afr[ks][mi][3],
                           r4[0], r4[1]);
                    mma_s8(acc0[mi][2*q+1][0], acc0[mi][2*q+1][1],
                           acc0[mi][2*q+1][2], acc0[mi][2*q+1][3],
                           afr[ks][mi][0], afr[ks][mi][1], afr[ks][mi][2], afr[ks][mi][3],
                           r4[2], r4[3]);
                }
            }
            if (c > 0)   // hide prev-chunk half-1 epilogue under these MMAs
                epi(acc1[0][ks], acc1[1][ks], bzB[ks], szB[ks]);
        }

        // reload bzB/szB for THIS chunk's j4..7 (used next iteration + final)
        #pragma unroll
        for (int jj = 0; jj < 4; jj++) {
            bzB[jj] = *(const float2*)(biasp + bcol + (4 + jj) * 8);
            szB[jj] = *(const float2*)(selp  + bcol + (4 + jj) * 8);
        }

        // ---- half 1 MMA (j 4..7) interleaved with EPI(this chunk half 0) ----
        #pragma unroll
        for (int mi = 0; mi < 2; mi++)
            #pragma unroll
            for (int jj = 0; jj < 4; jj++)
                #pragma unroll
                for (int e = 0; e < 4; e++)
                    acc1[mi][jj][e] = 0;

        #pragma unroll
        for (int ks = 0; ks < 4; ks++) {
            #pragma unroll
            for (int q = 2; q < 4; q++) {
                uint32_t r4[4];
                ldsm4(r4, sBcur + bofs + q * 16 * STRIDE + ks * 32);
                #pragma unroll
                for (int mi = 0; mi < 2; mi++) {
                    int jj0 = 2 * (q - 2);
                    mma_s8(acc1[mi][jj0][0],   acc1[mi][jj0][1],
                           acc1[mi][jj0][2],   acc1[mi][jj0][3],
                           afr[ks][mi][0], afr[ks][mi][1], afr[ks][mi][2], afr[ks][mi][3],
                           r4[0], r4[1]);
                    mma_s8(acc1[mi][jj0+1][0], acc1[mi][jj0+1][1],
                           acc1[mi][jj0+1][2], acc1[mi][jj0+1][3],
                           afr[ks][mi][0], afr[ks][mi][1], afr[ks][mi][2], afr[ks][mi][3],
                           r4[2], r4[3]);
                }
            }
            epi(acc0[0][ks], acc0[1][ks], bzA[ks], szA[ks]);
        }

        CP_WAIT0();
        __syncthreads();
    }

    // final exposed epilogue: last chunk's half 1
    #pragma unroll
    for (int ks = 0; ks < 4; ks++)
        epi(acc1[0][ks], acc1[1][ks], bzB[ks], szB[ks]);

    // ---- reduce across lane quads ----
    #pragma unroll
    for (int slot = 0; slot < 4; slot++) {
        s[slot] += __shfl_xor_sync(0xFFFFFFFFu, s[slot], 1);
        s[slot] += __shfl_xor_sync(0xFFFFFFFFu, s[slot], 2);
    }

    if ((lane & 3) == 0) {
        const int part = split * 2 + wn;
        #pragma unroll
        for (int slot = 0; slot < 4; slot++) {
            int row = rowtile * 128 + wm * 32 + (slot >> 1) * 16 + (lane >> 2)
                    + (slot & 1) * 8;
            g_s[row * SPLITS2 + part] = s[slot];
        }
    }
}

// ===================== kernel 4/5: merge + mean NLL ========================
__global__ void reduce1_kernel() {
    __shared__ float red[128];
    const int tid = threadIdx.x;
    const int row = blockIdx.x * 128 + tid;
    float ssum = 0.f;
    #pragma unroll
    for (int sp = 0; sp < SPLITS2; ++sp)
        ssum += g_s[row * SPLITS2 + sp];
    red[tid] = SHIFT_C + logf(ssum) - g_t[row];
    __syncthreads();
    #pragma unroll
    for (int off = 64; off > 0; off >>= 1) {
        if (tid < off) red[tid] += red[tid + off];
        __syncthreads();
    }
    if (tid == 0) g_red[blockIdx.x] = red[0];
}

__global__ void reduce2_kernel(float* __restrict__ out) {
    int t = threadIdx.x;
    float v = (t < 16) ? g_red[t] : 0.f;
    #pragma unroll
    for (int off = 16; off > 0; off >>= 1)
        v += __shfl_xor_sync(0xFFFFFFFFu, v, off);
    if (t == 0) out[0] = v / (float)B_ROWS;
}

// ============================ launch ======================================
extern "C" void kernel_launch(void* const* d_in, const int* in_sizes, int n_in,
                              void* d_out, int out_size) {
    const float* A    = (const float*)d_in[0];   // [2048, 128]
    const float* E    = (const float*)d_in[1];   // [100000, 128]
    const float* bias = (const float*)d_in[2];   // [100000]
    const void*  y    = d_in[3];                 // [2048] int64 or int32

    cudaFuncSetAttribute(main_kernel,
                         cudaFuncAttributeMaxDynamicSharedMemorySize, SM_TOTAL);

    const int totalW = B_ROWS + NE_PAD;          // one warp per row
    quant_kernel<<<(totalW * 32 + 255) / 256, 256>>>(A, E, bias);
    target_kernel<<<64, 1024>>>(A, E, bias, y);
    main_kernel<<<dim3(SPLITS, ROWTILES), 256, SM_TOTAL>>>();
    reduce1_kernel<<<16, 128>>>();
    reduce2_kernel<<<1, 32>>>((float*)d_out);
}

// round 6
// speedup vs baseline: 2.0481x; 2.0481x over previous
#include <cuda_runtime.h>
#include <cuda_bf16.h>
#include <cstdint>

// ============================ problem constants ============================
#define B_ROWS   2048
#define DIM      128
#define NE       100000
#define NE_PAD   100096            // 782 * 128
#define CHUNKS   782
#define SPLITS   9
#define CPS      87                // ceil(782/9)
#define ROWTILES 16
#define SPLITS2  (SPLITS * 2)
#define SHIFT_C  96.0f
#define L2E      1.44269504088896f

// ============================ device scratch ===============================
__device__ __align__(16) __nv_bfloat16 g_A[B_ROWS * DIM];
__device__ __align__(16) __nv_bfloat16 g_E[(size_t)NE_PAD * DIM];
__device__ float g_badj[NE_PAD];         // (bias - 96) * log2(e); pad = -1e30
__device__ float g_s[B_ROWS * SPLITS2];
__device__ float g_t[B_ROWS];
__device__ float g_red[16];

// ============================ PTX helpers ==================================
__device__ __forceinline__ uint32_t smem_to_u32(const void* smem_ptr) {
    uint32_t addr;
    asm("{ .reg .u64 tmp; cvta.to.shared.u64 tmp, %1; cvt.u32.u64 %0, tmp; }"
        : "=r"(addr) : "l"(smem_ptr));
    return addr;
}

__device__ __forceinline__ float ex2(float x) {
    float y;
    asm("ex2.approx.f32 %0, %1;" : "=f"(y) : "f"(x));
    return y;
}

__device__ __forceinline__ void cp16(uint32_t saddr, const void* gaddr) {
    asm volatile("cp.async.cg.shared.global [%0], [%1], 16;"
                 :: "r"(saddr), "l"(gaddr) : "memory");
}
#define CP_COMMIT() asm volatile("cp.async.commit_group;" ::: "memory")
#define CP_WAIT0()  asm volatile("cp.async.wait_group 0;" ::: "memory")

__device__ __forceinline__ void ldsm4(uint32_t* r, uint32_t addr) {
    asm volatile("ldmatrix.sync.aligned.m8n8.x4.shared.b16 {%0,%1,%2,%3}, [%4];"
                 : "=r"(r[0]), "=r"(r[1]), "=r"(r[2]), "=r"(r[3]) : "r"(addr));
}

__device__ __forceinline__ void mma_bf16(float& d0, float& d1, float& d2, float& d3,
                                         uint32_t a0, uint32_t a1, uint32_t a2, uint32_t a3,
                                         uint32_t b0, uint32_t b1) {
    asm volatile(
        "mma.sync.aligned.m16n8k16.row.col.f32.bf16.bf16.f32 "
        "{%0,%1,%2,%3}, {%4,%5,%6,%7}, {%8,%9}, {%0,%1,%2,%3};"
        : "+f"(d0), "+f"(d1), "+f"(d2), "+f"(d3)
        : "r"(a0), "r"(a1), "r"(a2), "r"(a3), "r"(b0), "r"(b1));
}

// ============================ SMEM layout ==================================
#define STRIDE   272                     // 256B row + 16B pad (conflict-free ldsm)
#define SM_A     0                       // 128 * 272 = 34816
#define SM_B0    34816
#define SM_B1    (34816 * 2)
#define SM_BIAS0 (34816 * 3)             // 104448
#define SM_BIAS1 (104448 + 512)
#define SM_TOTAL (104448 + 1024)

// ============================ kernel 1: convert ============================
__global__ void prep_kernel(const float* __restrict__ A,
                            const float* __restrict__ E,
                            const float* __restrict__ bias) {
    int tid = blockIdx.x * blockDim.x + threadIdx.x;
    int stride = gridDim.x * blockDim.x;

    for (int i = tid; i < B_ROWS * DIM; i += stride)
        g_A[i] = __float2bfloat16(A[i]);

    const int realE = NE * DIM;
    const int padE  = NE_PAD * DIM;
    for (int i = tid; i < padE; i += stride)
        g_E[i] = __float2bfloat16(i < realE ? E[i] : 0.0f);

    for (int i = tid; i < NE_PAD; i += stride)
        g_badj[i] = (i < NE) ? (bias[i] - SHIFT_C) * L2E : -1e30f;
}

// ===================== kernel 2: target logits (fp32) ======================
__global__ void target_kernel(const float* __restrict__ A,
                              const float* __restrict__ E,
                              const float* __restrict__ bias,
                              const void* __restrict__ yraw) {
    int gwarp = (blockIdx.x * blockDim.x + threadIdx.x) >> 5;
    int lane  = threadIdx.x & 31;
    if (gwarp >= B_ROWS) return;

    const int* y32 = (const int*)yraw;
    bool is64 = (y32[1] == 0) && (y32[3] == 0) && (y32[5] == 0);
    long long idx;
    if (is64) idx = ((const long long*)yraw)[gwarp];
    else      idx = (long long)y32[gwarp];

    const float4* a = (const float4*)(A + (size_t)gwarp * DIM);
    const float4* e = (const float4*)(E + (size_t)idx * DIM);
    float4 av = a[lane];
    float4 ev = e[lane];
    float d = av.x * ev.x + av.y * ev.y + av.z * ev.z + av.w * ev.w;
    #pragma unroll
    for (int off = 16; off > 0; off >>= 1)
        d += __shfl_xor_sync(0xFFFFFFFFu, d, off);
    if (lane == 0)
        g_t[gwarp] = d + bias[idx];
}

// ======== kernel 3: fused GEMM + fixed-shift softmax, EPI||MMA =============
__device__ __forceinline__ void load_chunk(uint32_t sb, int buf, int eb, int tid) {
    uint32_t dstB = sb + (buf ? SM_B1 : SM_B0);
    const __nv_bfloat16* src = g_E + (size_t)eb * DIM;
    #pragma unroll
    for (int t = 0; t < 8; t++) {
        int idx = tid + t * 256;
        int r   = idx >> 4;
        int seg = idx & 15;
        cp16(dstB + r * STRIDE + seg * 16, src + r * DIM + seg * 8);
    }
    if (tid < 32)
        cp16(sb + (buf ? SM_BIAS1 : SM_BIAS0) + tid * 16, g_badj + eb + tid * 4);
}

__global__ void __launch_bounds__(256, 1) main_kernel() {
    extern __shared__ char smem[];
    const uint32_t sb = smem_to_u32(smem);
    const int tid  = threadIdx.x;
    const int lane = tid & 31;
    const int wid  = tid >> 5;
    const int wm   = wid & 3;        // warp row-tile (32 rows)
    const int wn   = wid >> 2;       // warp col-tile (64 cols)
    const int split   = blockIdx.x;
    const int rowtile = blockIdx.y;

    const int start = split * CPS;
    const int count = min(CPS, CHUNKS - start);

    // ---- async load A tile + chunk 0 ----
    {
        const __nv_bfloat16* Abase = g_A + (size_t)rowtile * 128 * DIM;
        #pragma unroll
        for (int t = 0; t < 8; t++) {
            int idx = tid + t * 256;
            int r   = idx >> 4;
            int seg = idx & 15;
            cp16(sb + SM_A + r * STRIDE + seg * 16, Abase + r * DIM + seg * 8);
        }
    }
    load_chunk(sb, 0, start * 128, tid);
    CP_COMMIT();
    CP_WAIT0();
    __syncthreads();

    // ---- hoist A fragments: afr[ks][mi][4] ----
    uint32_t afr[8][2][4];
    {
        int g = lane >> 3, i = lane & 7;
        int row_add = (g & 1) * 8 + i;
        int col_add = (g >> 1) * 8;
        #pragma unroll
        for (int ks = 0; ks < 8; ks++)
            #pragma unroll
            for (int mi = 0; mi < 2; mi++) {
                int row = wm * 32 + mi * 16 + row_add;
                int col = ks * 16 + col_add;
                ldsm4(afr[ks][mi], sb + SM_A + row * STRIDE + col * 2);
            }
    }

    float s[4] = {0.f, 0.f, 0.f, 0.f};   // slot = mi*2 + h; rows r, r+8 per mi

    const int gB = lane >> 3, iB = lane & 7;
    const uint32_t bofs = (uint32_t)((wn * 64 + (gB >> 1) * 8 + iB) * STRIDE
                                     + (gB & 1) * 16);
    const int bcol = wn * 64 + (lane & 3) * 2;

    float accA[2][4][4];   // N half A: j 0..3
    float accB[2][4][4];   // N half B: j 4..7 (persists across chunk boundary)
    float2 bzA[4], bzB[4];

    // one EPI slice = (mi, j): 4 ex2 into s[mi*2] and s[mi*2+1]
    #define EPI_SLICE(ACC, BZ, MI, J) do {                                     \
        s[(MI)*2 + 0] += ex2(fmaf(ACC[MI][J][0], L2E, BZ[J].x))                \
                       + ex2(fmaf(ACC[MI][J][1], L2E, BZ[J].y));               \
        s[(MI)*2 + 1] += ex2(fmaf(ACC[MI][J][2], L2E, BZ[J].x))                \
                       + ex2(fmaf(ACC[MI][J][3], L2E, BZ[J].y));               \
    } while (0)

    for (int c = 0; c < count; ++c) {
        if (c + 1 < count)
            load_chunk(sb, (c + 1) & 1, (start + c + 1) * 128, tid);
        CP_COMMIT();

        const uint32_t sBcur = sb + ((c & 1) ? SM_B1 : SM_B0);
        const float* biasp = (const float*)(smem + ((c & 1) ? SM_BIAS1 : SM_BIAS0));

        #pragma unroll
        for (int jj = 0; jj < 4; jj++)
            bzA[jj] = *(const float2*)(biasp + bcol + jj * 8);

        // ---- half A MMA (j0..3) || EPI(prev chunk half B) ----
        #pragma unroll
        for (int mi = 0; mi < 2; mi++)
            #pragma unroll
            for (int jj = 0; jj < 4; jj++)
                #pragma unroll
                for (int e = 0; e < 4; e++)
                    accA[mi][jj][e] = 0.f;

        #pragma unroll
        for (int ks = 0; ks < 8; ks++) {
            uint32_t r0[4], r1[4];
            ldsm4(r0, sBcur + bofs + 0 * 16 * STRIDE + ks * 32);   // j0, j1
            ldsm4(r1, sBcur + bofs + 1 * 16 * STRIDE + ks * 32);   // j2, j3
            #pragma unroll
            for (int mi = 0; mi < 2; mi++) {
                mma_bf16(accA[mi][0][0], accA[mi][0][1], accA[mi][0][2], accA[mi][0][3],
                         afr[ks][mi][0], afr[ks][mi][1], afr[ks][mi][2], afr[ks][mi][3],
                         r0[0], r0[1]);
                mma_bf16(accA[mi][1][0], accA[mi][1][1], accA[mi][1][2], accA[mi][1][3],
                         afr[ks][mi][0], afr[ks][mi][1], afr[ks][mi][2], afr[ks][mi][3],
                         r0[2], r0[3]);
                mma_bf16(accA[mi][2][0], accA[mi][2][1], accA[mi][2][2], accA[mi][2][3],
                         afr[ks][mi][0], afr[ks][mi][1], afr[ks][mi][2], afr[ks][mi][3],
                         r1[0], r1[1]);
                mma_bf16(accA[mi][3][0], accA[mi][3][1], accA[mi][3][2], accA[mi][3][3],
                         afr[ks][mi][0], afr[ks][mi][1], afr[ks][mi][2], afr[ks][mi][3],
                         r1[2], r1[3]);
            }
            if (c > 0)     // retire prev chunk's half-B epilogue under these MMAs
                EPI_SLICE(accB, bzB, (ks >> 2), (ks & 3));
        }

        // bzB for THIS chunk (consumed next chunk / after loop)
        #pragma unroll
        for (int jj = 0; jj < 4; jj++)
            bzB[jj] = *(const float2*)(biasp + bcol + (4 + jj) * 8);

        // ---- half B MMA (j4..7) || EPI(this chunk half A) ----
        #pragma unroll
        for (int mi = 0; mi < 2; mi++)
            #pragma unroll
            for (int jj = 0; jj < 4; jj++)
                #pragma unroll
                for (int e = 0; e < 4; e++)
                    accB[mi][jj][e] = 0.f;

        #pragma unroll
        for (int ks = 0; ks < 8; ks++) {
            uint32_t r0[4], r1[4];
            ldsm4(r0, sBcur + bofs + 2 * 16 * STRIDE + ks * 32);   // j4, j5
            ldsm4(r1, sBcur + bofs + 3 * 16 * STRIDE + ks * 32);   // j6, j7
            #pragma unroll
            for (int mi = 0; mi < 2; mi++) {
                mma_bf16(accB[mi][0][0], accB[mi][0][1], accB[mi][0][2], accB[mi][0][3],
                         afr[ks][mi][0], afr[ks][mi][1], afr[ks][mi][2], afr[ks][mi][3],
                         r0[0], r0[1]);
                mma_bf16(accB[mi][1][0], accB[mi][1][1], accB[mi][1][2], accB[mi][1][3],
                         afr[ks][mi][0], afr[ks][mi][1], afr[ks][mi][2], afr[ks][mi][3],
                         r0[2], r0[3]);
                mma_bf16(accB[mi][2][0], accB[mi][2][1], accB[mi][2][2], accB[mi][2][3],
                         afr[ks][mi][0], afr[ks][mi][1], afr[ks][mi][2], afr[ks][mi][3],
                         r1[0], r1[1]);
                mma_bf16(accB[mi][3][0], accB[mi][3][1], accB[mi][3][2], accB[mi][3][3],
                         afr[ks][mi][0], afr[ks][mi][1], afr[ks][mi][2], afr[ks][mi][3],
                         r1[2], r1[3]);
            }
            EPI_SLICE(accA, bzA, (ks >> 2), (ks & 3));
        }

        CP_WAIT0();
        __syncthreads();
    }

    // retire final chunk's half-B epilogue
    #pragma unroll
    for (int mi = 0; mi < 2; mi++)
        #pragma unroll
        for (int jj = 0; jj < 4; jj++)
            EPI_SLICE(accB, bzB, mi, jj);

    // ---- reduce across lane quads ----
    #pragma unroll
    for (int slot = 0; slot < 4; slot++) {
        s[slot] += __shfl_xor_sync(0xFFFFFFFFu, s[slot], 1);
        s[slot] += __shfl_xor_sync(0xFFFFFFFFu, s[slot], 2);
    }

    if ((lane & 3) == 0) {
        const int part = split * 2 + wn;
        #pragma unroll
        for (int slot = 0; slot < 4; slot++) {
            int row = rowtile * 128 + wm * 32 + (slot >> 1) * 16 + (lane >> 2)
                    + (slot & 1) * 8;
            g_s[row * SPLITS2 + part] = s[slot];
        }
    }
}

// ===================== kernel 4/5: merge + mean NLL ========================
__global__ void reduce1_kernel() {
    __shared__ float red[128];
    const int tid = threadIdx.x;
    const int row = blockIdx.x * 128 + tid;
    float ssum = 0.f;
    #pragma unroll
    for (int sp = 0; sp < SPLITS2; ++sp)
        ssum += g_s[row * SPLITS2 + sp];
    red[tid] = SHIFT_C + logf(ssum) - g_t[row];
    __syncthreads();
    #pragma unroll
    for (int off = 64; off > 0; off >>= 1) {
        if (tid < off) red[tid] += red[tid + off];
        __syncthreads();
    }
    if (tid == 0) g_red[blockIdx.x] = red[0];
}

__global__ void reduce2_kernel(float* __restrict__ out) {
    int t = threadIdx.x;
    float v = (t < 16) ? g_red[t] : 0.f;
    #pragma unroll
    for (int off = 16; off > 0; off >>= 1)
        v += __shfl_xor_sync(0xFFFFFFFFu, v, off);
    if (t == 0) out[0] = v / (float)B_ROWS;
}

// ============================ launch ======================================
extern "C" void kernel_launch(void* const* d_in, const int* in_sizes, int n_in,
                              void* d_out, int out_size) {
    const float* A    = (const float*)d_in[0];   // [2048, 128]
    const float* E    = (const float*)d_in[1];   // [100000, 128]
    const float* bias = (const float*)d_in[2];   // [100000]
    const void*  y    = d_in[3];                 // [2048] int64 or int32

    cudaFuncSetAttribute(main_kernel,
                         cudaFuncAttributeMaxDynamicSharedMemorySize, SM_TOTAL);

    prep_kernel<<<512, 256>>>(A, E, bias);
    target_kernel<<<64, 1024>>>(A, E, bias, y);
    main_kernel<<<dim3(SPLITS, ROWTILES), 256, SM_TOTAL>>>();
    reduce1_kernel<<<16, 128>>>();
    reduce2_kernel<<<1, 32>>>((float*)d_out);
}